// round 14
// baseline (speedup 1.0000x reference)
#include <cuda_runtime.h>
#include <cuda_fp16.h>
#include <cstdint>

#define BATCH 64
#define VOCAB 16000
#define EMBED 256
#define DIMH  512
#define G3    1536
#define TSTEPS 63
#define GAMMA 0.1f
#define VC    128
#define NPB   125   // pred blocks = VOCAB / VC
#define EBIAS 10.0f

#define OUT_H_STRIDE (BATCH*DIMH)     // 32768
#define OUT_P_STRIDE (BATCH*VOCAB)    // 1024000
#define PRED_OFF (65*OUT_H_STRIDE)    // 2129920

// ---------------- scratch (device globals; no allocation) ----------------
__device__ __align__(16) float d_h[2][BATCH*DIMH];      // fp32 hidden state (row-major, ping-pong)
__device__ uint4 d_hfrag4[2][4096];    // fp16 h, A-frag layout [mt4][k16_32][lane32], 64KB each
__device__ uint4 d_xfrag4[2048];       // fp16 x, A-frag layout [mt4][k16_16][lane32], 32KB
__device__ __align__(16) float d_pE[NPB*BATCH*EMBED];   // partial E sums (fp32)
__device__ float d_pS[NPB*BATCH];                       // partial softmax denominators
// B-operand fp16 fragment layouts (precomputed once)
__device__ uint4 d_outwf4[1024000];   // [vb125][nt16][kq16][lane32]  (16 MB)
__device__ uint4 d_embf4[512000];     // [vb125][nt32][kq4][lane32]   (8 MB)
__device__ uint4 d_wihf4[49152];      // [gate3][jb64][kq8][lane32]
__device__ uint4 d_whhf4[98304];      // [gate3][jb64][kq16][lane32]

// ---------------- helpers ----------------
__device__ __forceinline__ unsigned f2h2(float lo, float hi) {
    __half2 h = __floats2half2_rn(lo, hi);
    return *(unsigned*)&h;
}

__device__ __forceinline__ void cp_async16(unsigned saddr, const uint4* g) {
    asm volatile("cp.async.cg.shared.global [%0], [%1], 16;" :: "r"(saddr), "l"(g));
}

// D(fp32) += A(fp16 16x16) * B(fp16 16x8)
__device__ __forceinline__ void mma16(float* c, uint4 a, unsigned b0, unsigned b1) {
    asm volatile(
        "mma.sync.aligned.m16n8k16.row.col.f32.f16.f16.f32 "
        "{%0,%1,%2,%3}, {%4,%5,%6,%7}, {%8,%9}, {%0,%1,%2,%3};\n"
        : "+f"(c[0]), "+f"(c[1]), "+f"(c[2]), "+f"(c[3])
        : "r"(a.x), "r"(a.y), "r"(a.z), "r"(a.w), "r"(b0), "r"(b1));
}

// half index of element (row m in 0..63, col k) within A-frag array of K16dim chunks
__device__ __forceinline__ int frag_h_idx(int m, int k, int K16dim) {
    int mt = m >> 4, mr = m & 15, k16 = k >> 4, kc = k & 15;
    int lane = ((mr & 7) << 2) | ((kc & 7) >> 1);
    int reg = ((mr >= 8) ? 1 : 0) | ((kc >= 8) ? 2 : 0);
    return (((mt * K16dim + k16) * 32 + lane) << 3) + (reg << 1) + (kc & 1);
}

// ---------------- prep: build fp16 fragment-layout weights ----------------
__global__ void prep_kernel(const float* __restrict__ outw, const float* __restrict__ emb,
                            const float* __restrict__ wih,  const float* __restrict__ whh) {
    const int N1 = 1024000;            // outwf4
    const int N2 = N1 + 512000;        // embf4
    const int N3 = N2 + 49152;         // wihf4
    const int N4 = N3 + 98304;         // whhf4
    for (int gid = blockIdx.x * blockDim.x + threadIdx.x; gid < N4;
         gid += gridDim.x * blockDim.x) {
        uint4 q;
        if (gid < N1) {
            int lane = gid & 31, kq = (gid >> 5) & 15, nt = (gid >> 9) & 15, vb = gid >> 13;
            int g = lane >> 2, tig = lane & 3;
            int n = vb * 128 + nt * 8 + g;
            const float* r = outw + n * DIMH + kq * 32 + 2 * tig;
            q.x = f2h2(r[0], r[1]);   q.y = f2h2(r[8], r[9]);
            q.z = f2h2(r[16], r[17]); q.w = f2h2(r[24], r[25]);
            d_outwf4[gid] = q;
        } else if (gid < N2) {
            int id = gid - N1;
            int lane = id & 31, kq = (id >> 5) & 3, nt = (id >> 7) & 31, vb = id >> 12;
            int g = lane >> 2, tig = lane & 3;
            int n = nt * 8 + g;
            const float* r = emb + (int64_t)(vb * 128 + kq * 32 + 2 * tig) * EMBED + n;
            q.x = f2h2(r[0], r[EMBED]);
            q.y = f2h2(r[8 * EMBED], r[9 * EMBED]);
            q.z = f2h2(r[16 * EMBED], r[17 * EMBED]);
            q.w = f2h2(r[24 * EMBED], r[25 * EMBED]);
            d_embf4[id] = q;
        } else if (gid < N3) {
            int id = gid - N2;
            int lane = id & 31, kq = (id >> 5) & 7, jb = (id >> 8) & 63, gate = id >> 14;
            int g = lane >> 2, tig = lane & 3;
            int row = gate * DIMH + jb * 8 + g;
            const float* r = wih + row * EMBED + kq * 32 + 2 * tig;
            q.x = f2h2(r[0], r[1]);   q.y = f2h2(r[8], r[9]);
            q.z = f2h2(r[16], r[17]); q.w = f2h2(r[24], r[25]);
            d_wihf4[id] = q;
        } else {
            int id = gid - N3;
            int lane = id & 31, kq = (id >> 5) & 15, jb = (id >> 9) & 63, gate = id >> 15;
            int g = lane >> 2, tig = lane & 3;
            int row = gate * DIMH + jb * 8 + g;
            const float* r = whh + row * DIMH + kq * 32 + 2 * tig;
            q.x = f2h2(r[0], r[1]);   q.y = f2h2(r[8], r[9]);
            q.z = f2h2(r[16], r[17]); q.w = f2h2(r[24], r[25]);
            d_whhf4[id] = q;
        }
    }
}

// ---------------- init: h0, x0, zero rows ----------------
__global__ void init_kernel(const float* __restrict__ z, const float* __restrict__ labels,
                            const float* __restrict__ emb, const float* __restrict__ fcw,
                            const float* __restrict__ fcb, float* __restrict__ out) {
    __half* hfh = (__half*)d_hfrag4[0];
    __half* xfh = (__half*)d_xfrag4;
    int64_t i = (int64_t)blockIdx.x * blockDim.x + threadIdx.x;
    int64_t stride = (int64_t)gridDim.x * blockDim.x;
    const int64_t NH0 = 32768;
    const int64_t NZ  = 65536;
    const int64_t NX  = 81920;
    const int64_t NP  = NX + (int64_t)OUT_P_STRIDE;
    for (; i < NP; i += stride) {
        if (i < NH0) {
            int b = (int)(i >> 9), j = (int)(i & 511);
            float v = (j < 64) ? (1.f - labels[b]) * fcw[j] + fcb[j]
                               : z[b * 448 + (j - 64)];
            d_h[0][i] = v; out[i] = v;
            hfh[frag_h_idx(b, j, 32)] = __float2half_rn(v);
        } else if (i < NZ) {
            out[i] = 0.f;
        } else if (i < NX) {
            int l = (int)(i - NZ); int b = l >> 8, c = l & 255;
            xfh[frag_h_idx(b, c, 16)] = __float2half_rn(emb[2 * EMBED + c]);  // IDX_SOS = 2
        } else {
            out[PRED_OFF + (i - NX)] = 0.f;
        }
    }
}

// ---------------- GRU cell: K-split over 8 warps (R9 form) ----------------
__global__ __launch_bounds__(256) void gru_kernel(int cur,
        const float* __restrict__ bih, const float* __restrict__ bhh,
        float* __restrict__ outh) {
    __shared__ float sAcc[4][32][12];
    const int nxt = cur ^ 1;
    int tid = threadIdx.x, lane = tid & 31, warp = tid >> 5;
    int mt = warp & 3, half = warp >> 2;
    int g = lane >> 2, tig = lane & 3;
    int jb = blockIdx.x;
    int j0 = jb * 8;
    int m0 = mt * 16;

    float acc[6][4];
    #pragma unroll
    for (int a = 0; a < 6; a++)
        #pragma unroll
        for (int b = 0; b < 4; b++) acc[a][b] = 0.f;

    const uint4* Ax = d_xfrag4 + mt * 512 + lane;
    const uint4* Ah = d_hfrag4[cur] + mt * 1024 + lane;
    const uint4* Bi = d_wihf4 + jb * 256 + lane;
    const uint4* Bh = d_whhf4 + jb * 512 + lane;

    if (half == 0) {
        #pragma unroll 4
        for (int kq = 0; kq < 8; kq++) {
            uint4 a0 = __ldg(&Ax[(2*kq)*32]), a1 = __ldg(&Ax[(2*kq+1)*32]);
            uint4 b0 = __ldg(&Bi[kq*32]);
            uint4 b1 = __ldg(&Bi[16384 + kq*32]);
            uint4 b2 = __ldg(&Bi[32768 + kq*32]);
            mma16(acc[0], a0, b0.x, b0.y); mma16(acc[0], a1, b0.z, b0.w);
            mma16(acc[1], a0, b1.x, b1.y); mma16(acc[1], a1, b1.z, b1.w);
            mma16(acc[2], a0, b2.x, b2.y); mma16(acc[2], a1, b2.z, b2.w);
        }
    }
    {
        const int kpBeg = (half == 0) ? 0 : 4;
        const int kpEnd = (half == 0) ? 4 : 16;
        #pragma unroll 4
        for (int kq = kpBeg; kq < kpEnd; kq++) {
            uint4 a0 = __ldg(&Ah[(2*kq)*32]), a1 = __ldg(&Ah[(2*kq+1)*32]);
            uint4 b0 = __ldg(&Bh[kq*32]);
            uint4 b1 = __ldg(&Bh[32768 + kq*32]);
            uint4 b2 = __ldg(&Bh[65536 + kq*32]);
            mma16(acc[3], a0, b0.x, b0.y); mma16(acc[3], a1, b0.z, b0.w);
            mma16(acc[4], a0, b1.x, b1.y); mma16(acc[4], a1, b1.z, b1.w);
            mma16(acc[5], a0, b2.x, b2.y); mma16(acc[5], a1, b2.z, b2.w);
        }
    }
    if (half == 1) {
        #pragma unroll
        for (int a = 0; a < 3; a++)
            #pragma unroll
            for (int b = 0; b < 4; b++) sAcc[mt][lane][a * 4 + b] = acc[3 + a][b];
    }
    __syncthreads();
    if (half == 0) {
        #pragma unroll
        for (int a = 0; a < 3; a++)
            #pragma unroll
            for (int b = 0; b < 4; b++) acc[3 + a][b] += sAcc[mt][lane][a * 4 + b];
        const float* hp = d_h[cur];
        float* hn = d_h[nxt];
        __half* hf = (__half*)d_hfrag4[nxt];
        #pragma unroll
        for (int idx = 0; idx < 4; idx++) {
            int m = m0 + g + ((idx & 2) ? 8 : 0);
            int j = j0 + 2 * tig + (idx & 1);
            float ir  = acc[0][idx] + bih[j];            float hr  = acc[3][idx] + bhh[j];
            float iz  = acc[1][idx] + bih[DIMH + j];     float hz  = acc[4][idx] + bhh[DIMH + j];
            float inn = acc[2][idx] + bih[2*DIMH + j];   float hnn = acc[5][idx] + bhh[2*DIMH + j];
            float r  = 1.f / (1.f + expf(-(ir + hr)));
            float zg = 1.f / (1.f + expf(-(iz + hz)));
            float nn = tanhf(inn + r * hnn);
            float hv = (1.f - zg) * nn + zg * hp[m * DIMH + j];
            hn[m * DIMH + j] = hv;
            __stcs(&outh[m * DIMH + j], hv);
            hf[frag_h_idx(m, j, 32)] = __float2half_rn(hv);
        }
    }
}

// ---------------- pred + softmax partials per 128-vocab block ----------------
// block = 1024 threads = 32 warps: mt = warp&3 (M tile), nh = warp>>2 (16-col vocab slice)
// phase-1 B staged per nh-group (4 warps) via cp.async DEPTH-3 ring, named-barrier sync.
// Total static smem = 24KB ring + 2KB sS2 = 26KB -> stays in the 32KB carveout bucket.
#define DEPTH 3
__global__ __launch_bounds__(1024, 1) void pred_kernel(int parity,
        const float* __restrict__ gum, const float* __restrict__ outb,
        float* __restrict__ predout) {
    __shared__ __align__(16) uint4 sRing[DEPTH][8][2][32];   // 24KB; aliased as sEf later
    __shared__ float sS2[64][8];
    int tid = threadIdx.x, lane = tid & 31, warp = tid >> 5;
    int g = lane >> 2, tig = lane & 3;
    int mt = warp & 3, nh = warp >> 2;     // nh in 0..7
    int vb = blockIdx.x;

    // ---- hoisted epilogue inputs (consumed ~phase-1-duration later) ----
    int rA = mt * 16 + g, rB = rA + 8;
    int vg0 = vb * 128 + nh * 16 + 2 * tig;   // nt=0 columns
    const float2 gA0 = __ldcs((const float2*)&gum[rA * VOCAB + vg0]);
    const float2 gA1 = __ldcs((const float2*)&gum[rA * VOCAB + vg0 + 8]);
    const float2 gB0 = __ldcs((const float2*)&gum[rB * VOCAB + vg0]);
    const float2 gB1 = __ldcs((const float2*)&gum[rB * VOCAB + vg0 + 8]);

    // ---- phase 1: pred = h @ out_w^T  (M=64, N per warp = 16, K=512) ----
    float pacc[2][4];
    #pragma unroll
    for (int a = 0; a < 2; a++)
        #pragma unroll
        for (int b = 0; b < 4; b++) pacc[a][b] = 0.f;

    const uint4* Af = d_hfrag4[parity] + mt * 1024 + lane;

    // producers: warps mt<2 of each nh group; warp mt stages nt=mt slice
    const bool prod = (mt < 2);
    const uint4* gSrc = d_outwf4 + vb * 8192 + nh * 1024 + mt * 512 + lane;
    unsigned sDst = (unsigned)__cvta_generic_to_shared(&sRing[0][nh][mt][lane]);
    const unsigned slotB = 8 * 2 * 32 * 16;   // 8192 bytes per stage

    if (prod) {
        #pragma unroll
        for (int s = 0; s < DEPTH - 1; s++) {
            cp_async16(sDst + s * slotB, gSrc + s * 32);
            asm volatile("cp.async.commit_group;");
        }
    }

    {
        uint4 a0 = __ldg(&Af[0]), a1 = __ldg(&Af[32]);
        int st = 0;
        #pragma unroll 1
        for (int kq = 0; kq < 16; kq++) {
            if (prod) asm volatile("cp.async.wait_group %0;" :: "n"(DEPTH - 2));
            asm volatile("bar.sync %0, %1;" :: "r"(1 + nh), "r"(128) : "memory");
            uint4 b0 = sRing[st][nh][0][lane];
            uint4 b1 = sRing[st][nh][1][lane];
            int kqn = (kq + 1 < 16) ? kq + 1 : 15;
            uint4 a0n = __ldg(&Af[(2 * kqn) * 32]), a1n = __ldg(&Af[(2 * kqn + 1) * 32]);
            if (prod) {
                int kn = kq + DEPTH - 1;
                int stp = (st + DEPTH - 1 >= DEPTH) ? st - 1 : st + DEPTH - 1;  // (st+2)%3
                if (kn < 16) cp_async16(sDst + stp * slotB, gSrc + kn * 32);
                asm volatile("cp.async.commit_group;");
            }
            mma16(pacc[0], a0, b0.x, b0.y); mma16(pacc[0], a1, b0.z, b0.w);
            mma16(pacc[1], a0, b1.x, b1.y); mma16(pacc[1], a1, b1.z, b1.w);
            a0 = a0n; a1 = a1n;
            st = (st + 1 == DEPTH) ? 0 : st + 1;
        }
    }

    // ---- epilogue: pred out, e = exp(pred + g - EBIAS) (gum already in regs) ----
    unsigned eA[2], eB[2];
    float slo = 0.f, shi = 0.f;
    {
        float ob0 = __ldg(&outb[vg0]),     ob1 = __ldg(&outb[vg0 + 1]);
        float ob2 = __ldg(&outb[vg0 + 8]), ob3 = __ldg(&outb[vg0 + 9]);
        float p00 = pacc[0][0] + ob0, p01 = pacc[0][1] + ob1;
        float p10 = pacc[0][2] + ob0, p11 = pacc[0][3] + ob1;
        float q00 = pacc[1][0] + ob2, q01 = pacc[1][1] + ob3;
        float q10 = pacc[1][2] + ob2, q11 = pacc[1][3] + ob3;
        __stcs((float2*)&predout[rA * VOCAB + vg0], make_float2(p00, p01));
        __stcs((float2*)&predout[rB * VOCAB + vg0], make_float2(p10, p11));
        __stcs((float2*)&predout[rA * VOCAB + vg0 + 8], make_float2(q00, q01));
        __stcs((float2*)&predout[rB * VOCAB + vg0 + 8], make_float2(q10, q11));
        eA[0] = f2h2(__expf(p00 + gA0.x - EBIAS), __expf(p01 + gA0.y - EBIAS));
        eB[0] = f2h2(__expf(p10 + gB0.x - EBIAS), __expf(p11 + gB0.y - EBIAS));
        eA[1] = f2h2(__expf(q00 + gA1.x - EBIAS), __expf(q01 + gA1.y - EBIAS));
        eB[1] = f2h2(__expf(q10 + gB1.x - EBIAS), __expf(q11 + gB1.y - EBIAS));
        #pragma unroll
        for (int nt = 0; nt < 2; nt++) {
            float2 fA = __half22float2(*(__half2*)&eA[nt]);
            float2 fB = __half22float2(*(__half2*)&eB[nt]);
            slo += fA.x + fA.y; shi += fB.x + fB.y;
        }
    }
    __syncthreads();    // all groups done reading sRing; safe to alias as sEf

    unsigned* sEfu = (unsigned*)sRing;   // aliased: first 16KB of the ring
    #pragma unroll
    for (int nt = 0; nt < 2; nt++) {
        int idx32 = (((mt * 8 + nh) * 32 + lane) << 2) + nt * 2;
        sEfu[idx32] = eA[nt];
        sEfu[idx32 + 1] = eB[nt];
    }
    slo += __shfl_down_sync(0xffffffffu, slo, 1);
    slo += __shfl_down_sync(0xffffffffu, slo, 2);
    shi += __shfl_down_sync(0xffffffffu, shi, 1);
    shi += __shfl_down_sync(0xffffffffu, shi, 2);
    if (tig == 0) {
        sS2[rA][nh] = slo;
        sS2[rB][nh] = shi;
    }
    __syncthreads();
    if (tid < 64) {
        float s = 0.f;
        #pragma unroll
        for (int q = 0; q < 8; q++) s += sS2[tid][q];
        d_pS[vb * 64 + tid] = s;
    }

    // ---- phase 3: partial E = e @ emb_chunk  (M=64, N per warp = 32, K=128) ----
    const uint4* sE4 = (uint4*)sRing + mt * 256 + lane;             // k16 stride 32
    const uint4* Ef = d_embf4 + vb * 4096 + (nh * 4) * 128 + lane;  // t stride 128, kq stride 32
    float* pEblk = d_pE + vb * (BATCH * EMBED);

    float eacc[4][4];
    #pragma unroll
    for (int a = 0; a < 4; a++)
        #pragma unroll
        for (int b = 0; b < 4; b++) eacc[a][b] = 0.f;

    #pragma unroll
    for (int kq = 0; kq < 4; kq++) {
        uint4 a0 = sE4[(2 * kq) * 32];
        uint4 a1 = sE4[(2 * kq + 1) * 32];
        #pragma unroll
        for (int t = 0; t < 4; t++) {
            uint4 be = __ldg(&Ef[t * 128 + kq * 32]);
            mma16(eacc[t], a0, be.x, be.y);
            mma16(eacc[t], a1, be.z, be.w);
        }
    }
    #pragma unroll
    for (int t = 0; t < 4; t++) {
        int c = (nh * 4 + t) * 8 + 2 * tig;
        __stcs((float2*)&pEblk[rA * EMBED + c], make_float2(eacc[t][0], eacc[t][1]));
        __stcs((float2*)&pEblk[rB * EMBED + c], make_float2(eacc[t][2], eacc[t][3]));
    }
}

// ---------------- reduce partials -> x_next (fp16 fragment layout) ----------------
__global__ __launch_bounds__(64) void reduce_kernel() {
    __shared__ float sred[64];
    int b = blockIdx.x, tid = threadIdx.x;
    float s = 0.f;
    for (int k = tid; k < NPB; k += 64) s += d_pS[k * 64 + b];
    sred[tid] = s;
    __syncthreads();
    #pragma unroll
    for (int off = 32; off > 0; off >>= 1) {
        if (tid < off) sred[tid] += sred[tid + off];
        __syncthreads();
    }
    float sinv = 1.f / (GAMMA * sred[0]);
    int c = blockIdx.y * 64 + tid;
    float acc = 0.f;
    const float* p = d_pE + b * EMBED + c;
    #pragma unroll 25
    for (int k = 0; k < NPB; k++) acc += __ldcs(&p[k * (BATCH * EMBED)]);
    ((__half*)d_xfrag4)[frag_h_idx(b, c, 16)] = __float2half_rn(acc * sinv);
}

// ---------------- launch ----------------
extern "C" void kernel_launch(void* const* d_in, const int* in_sizes, int n_in,
                              void* d_out, int out_size) {
    const float* z      = (const float*)d_in[0];
    const float* labels = (const float*)d_in[1];
    // d_in[2] src, d_in[3] src_len: unused by the transfered=True path
    const float* gum    = (const float*)d_in[4];
    const float* emb    = (const float*)d_in[5];
    const float* fcw    = (const float*)d_in[6];
    const float* fcb    = (const float*)d_in[7];
    const float* wih    = (const float*)d_in[8];
    const float* whh    = (const float*)d_in[9];
    const float* bih    = (const float*)d_in[10];
    const float* bhh    = (const float*)d_in[11];
    const float* outw   = (const float*)d_in[12];
    const float* outb   = (const float*)d_in[13];
    float* out = (float*)d_out;

    prep_kernel<<<2048, 256>>>(outw, emb, wih, whh);
    init_kernel<<<1024, 256>>>(z, labels, emb, fcw, fcb, out);

    for (int i = 0; i < TSTEPS; i++) {
        int cur = i & 1, nxt = cur ^ 1;
        gru_kernel<<<64, 256>>>(cur, bih, bhh, out + (int64_t)(2 + i) * OUT_H_STRIDE);
        pred_kernel<<<NPB, 1024>>>(nxt, gum + (int64_t)i * OUT_P_STRIDE,
                                   outb, out + PRED_OFF + (int64_t)(i + 1) * OUT_P_STRIDE);
        if (i < TSTEPS - 1) reduce_kernel<<<dim3(64, 4), 64>>>();
    }
}

// round 15
// speedup vs baseline: 1.5975x; 1.5975x over previous
#include <cuda_runtime.h>
#include <cuda_fp16.h>
#include <cstdint>

#define BATCH 64
#define VOCAB 16000
#define EMBED 256
#define DIMH  512
#define G3    1536
#define TSTEPS 63
#define GAMMA 0.1f
#define VC    128
#define NPB   125   // pred blocks = VOCAB / VC
#define EBIAS 10.0f

#define OUT_H_STRIDE (BATCH*DIMH)     // 32768
#define OUT_P_STRIDE (BATCH*VOCAB)    // 1024000
#define PRED_OFF (65*OUT_H_STRIDE)    // 2129920

// ---------------- scratch (device globals; no allocation) ----------------
__device__ __align__(16) float d_h[2][BATCH*DIMH];      // fp32 hidden state (row-major, ping-pong)
__device__ uint4 d_hfrag4[2][4096];    // fp16 h, A-frag layout [mt4][k16_32][lane32], 64KB each
__device__ uint4 d_xfrag4[2048];       // fp16 x, A-frag layout [mt4][k16_16][lane32], 32KB
__device__ __align__(16) float d_pE[NPB*BATCH*EMBED];   // partial E sums (fp32)
__device__ float d_pS[NPB*BATCH];                       // partial softmax denominators
// B-operand fp16 fragment layouts (precomputed once)
__device__ uint4 d_outwf4[1024000];   // [vb125][nt16][kq16][lane32]  (16 MB)
__device__ uint4 d_embf4[512000];     // [vb125][nt32][kq4][lane32]   (8 MB)
__device__ uint4 d_wihf4[49152];      // [gate3][jb64][kq8][lane32]
__device__ uint4 d_whhf4[98304];      // [gate3][jb64][kq16][lane32]

// ---------------- helpers ----------------
__device__ __forceinline__ unsigned f2h2(float lo, float hi) {
    __half2 h = __floats2half2_rn(lo, hi);
    return *(unsigned*)&h;
}

// D(fp32) += A(fp16 16x16) * B(fp16 16x8)
__device__ __forceinline__ void mma16(float* c, uint4 a, unsigned b0, unsigned b1) {
    asm volatile(
        "mma.sync.aligned.m16n8k16.row.col.f32.f16.f16.f32 "
        "{%0,%1,%2,%3}, {%4,%5,%6,%7}, {%8,%9}, {%0,%1,%2,%3};\n"
        : "+f"(c[0]), "+f"(c[1]), "+f"(c[2]), "+f"(c[3])
        : "r"(a.x), "r"(a.y), "r"(a.z), "r"(a.w), "r"(b0), "r"(b1));
}

// half index of element (row m in 0..63, col k) within A-frag array of K16dim chunks
__device__ __forceinline__ int frag_h_idx(int m, int k, int K16dim) {
    int mt = m >> 4, mr = m & 15, k16 = k >> 4, kc = k & 15;
    int lane = ((mr & 7) << 2) | ((kc & 7) >> 1);
    int reg = ((mr >= 8) ? 1 : 0) | ((kc >= 8) ? 2 : 0);
    return (((mt * K16dim + k16) * 32 + lane) << 3) + (reg << 1) + (kc & 1);
}

// ---------------- prep: build fp16 fragment-layout weights ----------------
__global__ void prep_kernel(const float* __restrict__ outw, const float* __restrict__ emb,
                            const float* __restrict__ wih,  const float* __restrict__ whh) {
    const int N1 = 1024000;            // outwf4
    const int N2 = N1 + 512000;        // embf4
    const int N3 = N2 + 49152;         // wihf4
    const int N4 = N3 + 98304;         // whhf4
    for (int gid = blockIdx.x * blockDim.x + threadIdx.x; gid < N4;
         gid += gridDim.x * blockDim.x) {
        uint4 q;
        if (gid < N1) {
            int lane = gid & 31, kq = (gid >> 5) & 15, nt = (gid >> 9) & 15, vb = gid >> 13;
            int g = lane >> 2, tig = lane & 3;
            int n = vb * 128 + nt * 8 + g;
            const float* r = outw + n * DIMH + kq * 32 + 2 * tig;
            q.x = f2h2(r[0], r[1]);   q.y = f2h2(r[8], r[9]);
            q.z = f2h2(r[16], r[17]); q.w = f2h2(r[24], r[25]);
            d_outwf4[gid] = q;
        } else if (gid < N2) {
            int id = gid - N1;
            int lane = id & 31, kq = (id >> 5) & 3, nt = (id >> 7) & 31, vb = id >> 12;
            int g = lane >> 2, tig = lane & 3;
            int n = nt * 8 + g;
            const float* r = emb + (int64_t)(vb * 128 + kq * 32 + 2 * tig) * EMBED + n;
            q.x = f2h2(r[0], r[EMBED]);
            q.y = f2h2(r[8 * EMBED], r[9 * EMBED]);
            q.z = f2h2(r[16 * EMBED], r[17 * EMBED]);
            q.w = f2h2(r[24 * EMBED], r[25 * EMBED]);
            d_embf4[id] = q;
        } else if (gid < N3) {
            int id = gid - N2;
            int lane = id & 31, kq = (id >> 5) & 7, jb = (id >> 8) & 63, gate = id >> 14;
            int g = lane >> 2, tig = lane & 3;
            int row = gate * DIMH + jb * 8 + g;
            const float* r = wih + row * EMBED + kq * 32 + 2 * tig;
            q.x = f2h2(r[0], r[1]);   q.y = f2h2(r[8], r[9]);
            q.z = f2h2(r[16], r[17]); q.w = f2h2(r[24], r[25]);
            d_wihf4[id] = q;
        } else {
            int id = gid - N3;
            int lane = id & 31, kq = (id >> 5) & 15, jb = (id >> 9) & 63, gate = id >> 15;
            int g = lane >> 2, tig = lane & 3;
            int row = gate * DIMH + jb * 8 + g;
            const float* r = whh + row * DIMH + kq * 32 + 2 * tig;
            q.x = f2h2(r[0], r[1]);   q.y = f2h2(r[8], r[9]);
            q.z = f2h2(r[16], r[17]); q.w = f2h2(r[24], r[25]);
            d_whhf4[id] = q;
        }
    }
}

// ---------------- init: h0, x0, zero rows ----------------
__global__ void init_kernel(const float* __restrict__ z, const float* __restrict__ labels,
                            const float* __restrict__ emb, const float* __restrict__ fcw,
                            const float* __restrict__ fcb, float* __restrict__ out) {
    __half* hfh = (__half*)d_hfrag4[0];
    __half* xfh = (__half*)d_xfrag4;
    int64_t i = (int64_t)blockIdx.x * blockDim.x + threadIdx.x;
    int64_t stride = (int64_t)gridDim.x * blockDim.x;
    const int64_t NH0 = 32768;
    const int64_t NZ  = 65536;
    const int64_t NX  = 81920;
    const int64_t NP  = NX + (int64_t)OUT_P_STRIDE;
    for (; i < NP; i += stride) {
        if (i < NH0) {
            int b = (int)(i >> 9), j = (int)(i & 511);
            float v = (j < 64) ? (1.f - labels[b]) * fcw[j] + fcb[j]
                               : z[b * 448 + (j - 64)];
            d_h[0][i] = v; out[i] = v;
            hfh[frag_h_idx(b, j, 32)] = __float2half_rn(v);
        } else if (i < NZ) {
            out[i] = 0.f;
        } else if (i < NX) {
            int l = (int)(i - NZ); int b = l >> 8, c = l & 255;
            xfh[frag_h_idx(b, c, 16)] = __float2half_rn(emb[2 * EMBED + c]);  // IDX_SOS = 2
        } else {
            out[PRED_OFF + (i - NX)] = 0.f;
        }
    }
}

// ---------------- GRU cell: K-split over 8 warps (R9 form) ----------------
__global__ __launch_bounds__(256) void gru_kernel(int cur,
        const float* __restrict__ bih, const float* __restrict__ bhh,
        float* __restrict__ outh) {
    __shared__ float sAcc[4][32][12];
    const int nxt = cur ^ 1;
    int tid = threadIdx.x, lane = tid & 31, warp = tid >> 5;
    int mt = warp & 3, half = warp >> 2;
    int g = lane >> 2, tig = lane & 3;
    int jb = blockIdx.x;
    int j0 = jb * 8;
    int m0 = mt * 16;

    float acc[6][4];
    #pragma unroll
    for (int a = 0; a < 6; a++)
        #pragma unroll
        for (int b = 0; b < 4; b++) acc[a][b] = 0.f;

    const uint4* Ax = d_xfrag4 + mt * 512 + lane;
    const uint4* Ah = d_hfrag4[cur] + mt * 1024 + lane;
    const uint4* Bi = d_wihf4 + jb * 256 + lane;
    const uint4* Bh = d_whhf4 + jb * 512 + lane;

    if (half == 0) {
        #pragma unroll 4
        for (int kq = 0; kq < 8; kq++) {
            uint4 a0 = __ldg(&Ax[(2*kq)*32]), a1 = __ldg(&Ax[(2*kq+1)*32]);
            uint4 b0 = __ldg(&Bi[kq*32]);
            uint4 b1 = __ldg(&Bi[16384 + kq*32]);
            uint4 b2 = __ldg(&Bi[32768 + kq*32]);
            mma16(acc[0], a0, b0.x, b0.y); mma16(acc[0], a1, b0.z, b0.w);
            mma16(acc[1], a0, b1.x, b1.y); mma16(acc[1], a1, b1.z, b1.w);
            mma16(acc[2], a0, b2.x, b2.y); mma16(acc[2], a1, b2.z, b2.w);
        }
    }
    {
        const int kpBeg = (half == 0) ? 0 : 4;
        const int kpEnd = (half == 0) ? 4 : 16;
        #pragma unroll 4
        for (int kq = kpBeg; kq < kpEnd; kq++) {
            uint4 a0 = __ldg(&Ah[(2*kq)*32]), a1 = __ldg(&Ah[(2*kq+1)*32]);
            uint4 b0 = __ldg(&Bh[kq*32]);
            uint4 b1 = __ldg(&Bh[32768 + kq*32]);
            uint4 b2 = __ldg(&Bh[65536 + kq*32]);
            mma16(acc[3], a0, b0.x, b0.y); mma16(acc[3], a1, b0.z, b0.w);
            mma16(acc[4], a0, b1.x, b1.y); mma16(acc[4], a1, b1.z, b1.w);
            mma16(acc[5], a0, b2.x, b2.y); mma16(acc[5], a1, b2.z, b2.w);
        }
    }
    if (half == 1) {
        #pragma unroll
        for (int a = 0; a < 3; a++)
            #pragma unroll
            for (int b = 0; b < 4; b++) sAcc[mt][lane][a * 4 + b] = acc[3 + a][b];
    }
    __syncthreads();
    if (half == 0) {
        #pragma unroll
        for (int a = 0; a < 3; a++)
            #pragma unroll
            for (int b = 0; b < 4; b++) acc[3 + a][b] += sAcc[mt][lane][a * 4 + b];
        const float* hp = d_h[cur];
        float* hn = d_h[nxt];
        __half* hf = (__half*)d_hfrag4[nxt];
        #pragma unroll
        for (int idx = 0; idx < 4; idx++) {
            int m = m0 + g + ((idx & 2) ? 8 : 0);
            int j = j0 + 2 * tig + (idx & 1);
            float ir  = acc[0][idx] + bih[j];            float hr  = acc[3][idx] + bhh[j];
            float iz  = acc[1][idx] + bih[DIMH + j];     float hz  = acc[4][idx] + bhh[DIMH + j];
            float inn = acc[2][idx] + bih[2*DIMH + j];   float hnn = acc[5][idx] + bhh[2*DIMH + j];
            float r  = 1.f / (1.f + expf(-(ir + hr)));
            float zg = 1.f / (1.f + expf(-(iz + hz)));
            float nn = tanhf(inn + r * hnn);
            float hv = (1.f - zg) * nn + zg * hp[m * DIMH + j];
            hn[m * DIMH + j] = hv;
            __stcs(&outh[m * DIMH + j], hv);
            hf[frag_h_idx(m, j, 32)] = __float2half_rn(hv);
        }
    }
}

// ---------------- pred + softmax partials per 128-vocab block ----------------
// block = 1024 threads = 32 warps: mt = warp&3 (M tile), nh = warp>>2 (16-col vocab slice)
// R9 form (register double-buffered phase 1, 18KB static smem) + hoisted gumbel loads.
__global__ __launch_bounds__(1024, 1) void pred_kernel(int parity,
        const float* __restrict__ gum, const float* __restrict__ outb,
        float* __restrict__ predout) {
    __shared__ __align__(16) uint4 sEf4[4 * 8 * 32];   // e fp16 A-frag layout, 16KB
    __shared__ float sS2[64][8];
    int tid = threadIdx.x, lane = tid & 31, warp = tid >> 5;
    int g = lane >> 2, tig = lane & 3;
    int mt = warp & 3, nh = warp >> 2;     // nh in 0..7
    int vb = blockIdx.x;

    // ---- hoisted epilogue inputs: issued here, consumed after phase 1 ----
    int rA = mt * 16 + g, rB = rA + 8;
    int vg0 = vb * 128 + nh * 16 + 2 * tig;
    const float2 gA0 = __ldcs((const float2*)&gum[rA * VOCAB + vg0]);
    const float2 gA1 = __ldcs((const float2*)&gum[rA * VOCAB + vg0 + 8]);
    const float2 gB0 = __ldcs((const float2*)&gum[rB * VOCAB + vg0]);
    const float2 gB1 = __ldcs((const float2*)&gum[rB * VOCAB + vg0 + 8]);

    // ---- phase 1: pred = h @ out_w^T  (M=64, N per warp = 16, K=512) ----
    float pacc[2][4];
    #pragma unroll
    for (int a = 0; a < 2; a++)
        #pragma unroll
        for (int b = 0; b < 4; b++) pacc[a][b] = 0.f;

    const uint4* Af = d_hfrag4[parity] + mt * 1024 + lane;
    const uint4* Bf = d_outwf4 + vb * 8192 + nh * 1024 + lane;  // nt stride 512, kq stride 32

    {
        uint4 a0 = __ldg(&Af[0]), a1 = __ldg(&Af[32]);
        uint4 c0 = __ldg(&Bf[0]), c1 = __ldg(&Bf[512]);
        #pragma unroll 1
        for (int kq = 0; kq < 16; kq++) {
            int kqn = (kq + 1 < 16) ? kq + 1 : 15;
            uint4 a0n = __ldg(&Af[(2*kqn)*32]), a1n = __ldg(&Af[(2*kqn+1)*32]);
            uint4 n0 = __ldg(&Bf[kqn*32]), n1 = __ldg(&Bf[512 + kqn*32]);
            mma16(pacc[0], a0, c0.x, c0.y); mma16(pacc[0], a1, c0.z, c0.w);
            mma16(pacc[1], a0, c1.x, c1.y); mma16(pacc[1], a1, c1.z, c1.w);
            a0 = a0n; a1 = a1n; c0 = n0; c1 = n1;
        }
    }

    // ---- epilogue: pred out, e = exp(pred + g - EBIAS) (gum already in regs) ----
    unsigned eA[2], eB[2];
    float slo = 0.f, shi = 0.f;
    {
        float ob0 = __ldg(&outb[vg0]),     ob1 = __ldg(&outb[vg0 + 1]);
        float ob2 = __ldg(&outb[vg0 + 8]), ob3 = __ldg(&outb[vg0 + 9]);
        float p00 = pacc[0][0] + ob0, p01 = pacc[0][1] + ob1;
        float p10 = pacc[0][2] + ob0, p11 = pacc[0][3] + ob1;
        float q00 = pacc[1][0] + ob2, q01 = pacc[1][1] + ob3;
        float q10 = pacc[1][2] + ob2, q11 = pacc[1][3] + ob3;
        __stcs((float2*)&predout[rA * VOCAB + vg0], make_float2(p00, p01));
        __stcs((float2*)&predout[rB * VOCAB + vg0], make_float2(p10, p11));
        __stcs((float2*)&predout[rA * VOCAB + vg0 + 8], make_float2(q00, q01));
        __stcs((float2*)&predout[rB * VOCAB + vg0 + 8], make_float2(q10, q11));
        eA[0] = f2h2(__expf(p00 + gA0.x - EBIAS), __expf(p01 + gA0.y - EBIAS));
        eB[0] = f2h2(__expf(p10 + gB0.x - EBIAS), __expf(p11 + gB0.y - EBIAS));
        eA[1] = f2h2(__expf(q00 + gA1.x - EBIAS), __expf(q01 + gA1.y - EBIAS));
        eB[1] = f2h2(__expf(q10 + gB1.x - EBIAS), __expf(q11 + gB1.y - EBIAS));
        #pragma unroll
        for (int nt = 0; nt < 2; nt++) {
            float2 fA = __half22float2(*(__half2*)&eA[nt]);
            float2 fB = __half22float2(*(__half2*)&eB[nt]);
            slo += fA.x + fA.y; shi += fB.x + fB.y;
        }
    }

    unsigned* sEfu = (unsigned*)sEf4;
    #pragma unroll
    for (int nt = 0; nt < 2; nt++) {
        int idx32 = (((mt * 8 + nh) * 32 + lane) << 2) + nt * 2;
        sEfu[idx32] = eA[nt];
        sEfu[idx32 + 1] = eB[nt];
    }
    slo += __shfl_down_sync(0xffffffffu, slo, 1);
    slo += __shfl_down_sync(0xffffffffu, slo, 2);
    shi += __shfl_down_sync(0xffffffffu, shi, 1);
    shi += __shfl_down_sync(0xffffffffu, shi, 2);
    if (tig == 0) {
        sS2[rA][nh] = slo;
        sS2[rB][nh] = shi;
    }
    __syncthreads();
    if (tid < 64) {
        float s = 0.f;
        #pragma unroll
        for (int q = 0; q < 8; q++) s += sS2[tid][q];
        d_pS[vb * 64 + tid] = s;
    }

    // ---- phase 3: partial E = e @ emb_chunk  (M=64, N per warp = 32, K=128) ----
    const uint4* sE4 = sEf4 + mt * 256 + lane;                      // k16 stride 32
    const uint4* Ef = d_embf4 + vb * 4096 + (nh * 4) * 128 + lane;  // t stride 128, kq stride 32
    float* pEblk = d_pE + vb * (BATCH * EMBED);

    float eacc[4][4];
    #pragma unroll
    for (int a = 0; a < 4; a++)
        #pragma unroll
        for (int b = 0; b < 4; b++) eacc[a][b] = 0.f;

    #pragma unroll
    for (int kq = 0; kq < 4; kq++) {
        uint4 a0 = sE4[(2 * kq) * 32];
        uint4 a1 = sE4[(2 * kq + 1) * 32];
        #pragma unroll
        for (int t = 0; t < 4; t++) {
            uint4 be = __ldg(&Ef[t * 128 + kq * 32]);
            mma16(eacc[t], a0, be.x, be.y);
            mma16(eacc[t], a1, be.z, be.w);
        }
    }
    #pragma unroll
    for (int t = 0; t < 4; t++) {
        int c = (nh * 4 + t) * 8 + 2 * tig;
        __stcs((float2*)&pEblk[rA * EMBED + c], make_float2(eacc[t][0], eacc[t][1]));
        __stcs((float2*)&pEblk[rB * EMBED + c], make_float2(eacc[t][2], eacc[t][3]));
    }
}

// ---------------- reduce partials -> x_next (fp16 fragment layout) ----------------
__global__ __launch_bounds__(64) void reduce_kernel() {
    __shared__ float sred[64];
    int b = blockIdx.x, tid = threadIdx.x;
    float s = 0.f;
    for (int k = tid; k < NPB; k += 64) s += d_pS[k * 64 + b];
    sred[tid] = s;
    __syncthreads();
    #pragma unroll
    for (int off = 32; off > 0; off >>= 1) {
        if (tid < off) sred[tid] += sred[tid + off];
        __syncthreads();
    }
    float sinv = 1.f / (GAMMA * sred[0]);
    int c = blockIdx.y * 64 + tid;
    float acc = 0.f;
    const float* p = d_pE + b * EMBED + c;
    #pragma unroll 25
    for (int k = 0; k < NPB; k++) acc += __ldcs(&p[k * (BATCH * EMBED)]);
    ((__half*)d_xfrag4)[frag_h_idx(b, c, 16)] = __float2half_rn(acc * sinv);
}

// ---------------- launch ----------------
extern "C" void kernel_launch(void* const* d_in, const int* in_sizes, int n_in,
                              void* d_out, int out_size) {
    const float* z      = (const float*)d_in[0];
    const float* labels = (const float*)d_in[1];
    // d_in[2] src, d_in[3] src_len: unused by the transfered=True path
    const float* gum    = (const float*)d_in[4];
    const float* emb    = (const float*)d_in[5];
    const float* fcw    = (const float*)d_in[6];
    const float* fcb    = (const float*)d_in[7];
    const float* wih    = (const float*)d_in[8];
    const float* whh    = (const float*)d_in[9];
    const float* bih    = (const float*)d_in[10];
    const float* bhh    = (const float*)d_in[11];
    const float* outw   = (const float*)d_in[12];
    const float* outb   = (const float*)d_in[13];
    float* out = (float*)d_out;

    prep_kernel<<<2048, 256>>>(outw, emb, wih, whh);
    init_kernel<<<1024, 256>>>(z, labels, emb, fcw, fcb, out);

    for (int i = 0; i < TSTEPS; i++) {
        int cur = i & 1, nxt = cur ^ 1;
        gru_kernel<<<64, 256>>>(cur, bih, bhh, out + (int64_t)(2 + i) * OUT_H_STRIDE);
        pred_kernel<<<NPB, 1024>>>(nxt, gum + (int64_t)i * OUT_P_STRIDE,
                                   outb, out + PRED_OFF + (int64_t)(i + 1) * OUT_P_STRIDE);
        if (i < TSTEPS - 1) reduce_kernel<<<dim3(64, 4), 64>>>();
    }
}